// round 2
// baseline (speedup 1.0000x reference)
#include <cuda_runtime.h>
#include <cstdint>

// Problem constants
#define DIM    10
#define WIDTH  80
#define LEN_TH 971   // 10 + 10*80 + 80 + 80 + 1

// Offsets within a point's theta vector
#define OFF_BETA 0
#define OFF_A    10
#define OFF_B    810
#define OFF_C    890
#define OFF_D    970

#define PTS_PER_BLK 8
#define TH_FLOATS  (PTS_PER_BLK * LEN_TH)   // 7768 floats = 31072 bytes (16B-divisible)
#define TH_VEC4    (TH_FLOATS / 4)          // 1942 float4 loads per block

// One warp per point, 8 warps (256 threads) per block.
// theta is staged block-wide into shared memory with aligned float4 loads:
// per-point theta base is only 4B-aligned (971*4 % 16 == 12), but the
// 8-point block chunk (31072 B) is 16B-aligned, enabling LDG.128.
__global__ __launch_bounds__(256) void u5_kernel(
    const float* __restrict__ theta,
    const float* __restrict__ x,
    float* __restrict__ out,
    int n_points)
{
    __shared__ float s_th[TH_FLOATS];

    const int warp_in_block = threadIdx.x >> 5;
    const int lane = threadIdx.x & 31;
    const int p = blockIdx.x * PTS_PER_BLK + warp_in_block;

    // ---- Stage this block's theta chunk into smem with float4 loads ----
    {
        const size_t blk_base = (size_t)blockIdx.x * TH_FLOATS;
        const size_t total_floats = (size_t)n_points * LEN_TH;
        const float4* __restrict__ g = (const float4*)(theta + blk_base);
        float4* __restrict__ s = (float4*)s_th;
#pragma unroll
        for (int i = 0; i < 8; ++i) {
            int idx = threadIdx.x + 256 * i;
            if (idx < TH_VEC4 && blk_base + 4 * (size_t)idx + 3 < total_floats) {
                s[idx] = __ldg(&g[idx]);
            }
        }
    }
    __syncthreads();

    if (p >= n_points) return;

    const float* __restrict__ th = s_th + warp_in_block * LEN_TH;
    const float* __restrict__ xp = x + (size_t)p * DIM;

    // u0[d] = sin(pi * (x[d] - beta[d])), lanes 0..9 compute, broadcast
    float my_u0 = 0.0f;
    if (lane < DIM) {
        my_u0 = sinpif(xp[lane] - th[OFF_BETA + lane]);
    }

    float u0[DIM];
#pragma unroll
    for (int d = 0; d < DIM; ++d) {
        u0[d] = __shfl_sync(0xffffffffu, my_u0, d);
    }

    // Each lane accumulates width columns: lane, lane+32, and (lane<16) lane+64
    float acc0 = 0.0f, acc1 = 0.0f, acc2 = 0.0f;
    const float* __restrict__ A = th + OFF_A;
#pragma unroll
    for (int d = 0; d < DIM; ++d) {
        const float* __restrict__ row = A + d * WIDTH;
        acc0 = fmaf(u0[d], row[lane], acc0);
        acc1 = fmaf(u0[d], row[lane + 32], acc1);
        if (lane < 16)
            acc2 = fmaf(u0[d], row[lane + 64], acc2);
    }

    const float* __restrict__ B = th + OFF_B;
    const float* __restrict__ C = th + OFF_C;

    float h0 = tanhf(acc0 - B[lane]);
    float h1 = tanhf(acc1 - B[lane + 32]);
    float s  = h0 * C[lane] + h1 * C[lane + 32];
    if (lane < 16) {
        float h2 = tanhf(acc2 - B[lane + 64]);
        s = fmaf(h2, C[lane + 64], s);
    }

    // Warp reduction
#pragma unroll
    for (int off = 16; off > 0; off >>= 1)
        s += __shfl_xor_sync(0xffffffffu, s, off);

    if (lane == 0)
        out[p] = s - th[OFF_D];
}

extern "C" void kernel_launch(void* const* d_in, const int* in_sizes, int n_in,
                              void* d_out, int out_size)
{
    const float* theta = (const float*)d_in[0];
    const float* x     = (const float*)d_in[1];
    float* out = (float*)d_out;

    const int n_points = out_size;            // 256*1024 = 262144
    const int blocks = (n_points + PTS_PER_BLK - 1) / PTS_PER_BLK;

    u5_kernel<<<blocks, 256>>>(theta, x, out, n_points);
}

// round 3
// speedup vs baseline: 1.2902x; 1.2902x over previous
#include <cuda_runtime.h>
#include <cstdint>

// Problem constants
#define DIM    10
#define WIDTH  80
#define LEN_TH 971   // 10 + 10*80 + 80 + 80 + 1

#define OFF_BETA 0
#define OFF_A    10
#define OFF_B    810
#define OFF_C    890
#define OFF_D    970

// One warp per TWO consecutive points; 8 warps (256 threads) per block
// -> 16 points per block. The two points' load streams are interleaved to
// double per-warp MLP (~70 outstanding LDGs) and raise DRAM duty cycle.
__global__ __launch_bounds__(256) void u5_kernel(
    const float* __restrict__ theta,
    const float* __restrict__ x,
    float* __restrict__ out,
    int n_points)
{
    const int warp_in_block = threadIdx.x >> 5;
    const int lane = threadIdx.x & 31;
    const int p0 = (blockIdx.x * 8 + warp_in_block) * 2;
    const int p1 = p0 + 1;
    if (p0 >= n_points) return;
    const bool has_p1 = (p1 < n_points);

    const float* __restrict__ th0 = theta + (size_t)p0 * LEN_TH;
    const float* __restrict__ th1 = theta + (size_t)(has_p1 ? p1 : p0) * LEN_TH;
    const float* __restrict__ xp0 = x + (size_t)p0 * DIM;
    const float* __restrict__ xp1 = x + (size_t)(has_p1 ? p1 : p0) * DIM;

    // u0 for both points in one shuffle pass:
    // lanes 0..9  compute point0's sinpi, lanes 16..25 compute point1's.
    float my_u0 = 0.0f;
    if (lane < DIM) {
        my_u0 = sinpif(__ldcs(xp0 + lane) - __ldcs(th0 + OFF_BETA + lane));
    } else if (lane >= 16 && lane < 16 + DIM) {
        my_u0 = sinpif(__ldcs(xp1 + (lane - 16)) - __ldcs(th1 + OFF_BETA + (lane - 16)));
    }

    float u0a[DIM], u0b[DIM];
#pragma unroll
    for (int d = 0; d < DIM; ++d) {
        u0a[d] = __shfl_sync(0xffffffffu, my_u0, d);
        u0b[d] = __shfl_sync(0xffffffffu, my_u0, d + 16);
    }

    // Each lane owns width columns {lane, lane+32} and (lane<16) {lane+64},
    // for both points, interleaved.
    float a0_0 = 0.f, a0_1 = 0.f, a0_2 = 0.f;   // point0 accumulators
    float a1_0 = 0.f, a1_1 = 0.f, a1_2 = 0.f;   // point1 accumulators
    const float* __restrict__ A0 = th0 + OFF_A;
    const float* __restrict__ A1 = th1 + OFF_A;
#pragma unroll
    for (int d = 0; d < DIM; ++d) {
        const float* __restrict__ r0 = A0 + d * WIDTH;
        const float* __restrict__ r1 = A1 + d * WIDTH;
        a0_0 = fmaf(u0a[d], __ldcs(r0 + lane),      a0_0);
        a1_0 = fmaf(u0b[d], __ldcs(r1 + lane),      a1_0);
        a0_1 = fmaf(u0a[d], __ldcs(r0 + lane + 32), a0_1);
        a1_1 = fmaf(u0b[d], __ldcs(r1 + lane + 32), a1_1);
        if (lane < 16) {
            a0_2 = fmaf(u0a[d], __ldcs(r0 + lane + 64), a0_2);
            a1_2 = fmaf(u0b[d], __ldcs(r1 + lane + 64), a1_2);
        }
    }

    const float* __restrict__ B0 = th0 + OFF_B;
    const float* __restrict__ C0 = th0 + OFF_C;
    const float* __restrict__ B1 = th1 + OFF_B;
    const float* __restrict__ C1 = th1 + OFF_C;

    float s0, s1;
    {
        float h0 = tanhf(a0_0 - __ldcs(B0 + lane));
        float h1 = tanhf(a0_1 - __ldcs(B0 + lane + 32));
        s0 = h0 * __ldcs(C0 + lane) + h1 * __ldcs(C0 + lane + 32);
        if (lane < 16) {
            float h2 = tanhf(a0_2 - __ldcs(B0 + lane + 64));
            s0 = fmaf(h2, __ldcs(C0 + lane + 64), s0);
        }
    }
    {
        float h0 = tanhf(a1_0 - __ldcs(B1 + lane));
        float h1 = tanhf(a1_1 - __ldcs(B1 + lane + 32));
        s1 = h0 * __ldcs(C1 + lane) + h1 * __ldcs(C1 + lane + 32);
        if (lane < 16) {
            float h2 = tanhf(a1_2 - __ldcs(B1 + lane + 64));
            s1 = fmaf(h2, __ldcs(C1 + lane + 64), s1);
        }
    }

    // Warp reductions (independent, will interleave)
#pragma unroll
    for (int off = 16; off > 0; off >>= 1) {
        s0 += __shfl_xor_sync(0xffffffffu, s0, off);
        s1 += __shfl_xor_sync(0xffffffffu, s1, off);
    }

    if (lane == 0) {
        out[p0] = s0 - __ldcs(th0 + OFF_D);
        if (has_p1)
            out[p1] = s1 - __ldcs(th1 + OFF_D);
    }
}

extern "C" void kernel_launch(void* const* d_in, const int* in_sizes, int n_in,
                              void* d_out, int out_size)
{
    const float* theta = (const float*)d_in[0];
    const float* x     = (const float*)d_in[1];
    float* out = (float*)d_out;

    const int n_points = out_size;                 // 262144
    const int pts_per_block = 16;                  // 8 warps * 2 points
    const int blocks = (n_points + pts_per_block - 1) / pts_per_block;

    u5_kernel<<<blocks, 256>>>(theta, x, out, n_points);
}